// round 2
// baseline (speedup 1.0000x reference)
#include <cuda_runtime.h>
#include <math.h>

#define PI_D 3.141592653589793238462643383279502884

// ---------------- constant / scratch device globals (static: allocation-free) ----------------
__device__ double g_lg[64];            // log(k!)
__device__ double g_wq[128];           // SOFT quadrature weights
__device__ double g_cpin[128][40];     // cos(beta_j/2)^k, input betas
__device__ double g_spin[128][40];
__device__ double g_cpout[40][40];     // output betas
__device__ double g_spout[40][40];
__device__ float2 g_tw128[128];        // e^{-2pi i t/128}
__device__ float2 g_e40f[40];          // e^{+2pi i t/40}

__device__ float  g_ws2 [210*128];     // [lmh][j], m>=0 half, quadrature-weighted d^l_{m,0}
__device__ float  g_dinv[40*5530];     // [b][t], (2l+1)*d^l_{m,n}(beta_b), m>=0 half
__device__ float2 g_Fk  [24*400];      // [p][lmf]
__device__ float2 g_y   [400*512];     // [lmf][i*32+o]
__device__ float2 g_xf  [20*128*256];  // [m][j][zi]
__device__ float2 g_xl  [210*256];     // [lmh][zi]
__device__ float2 g_zl  [5530*512];    // [t][z*32+o]

// prefix offsets T_l = sum_{k<l} (k+1)(2k+1)  (m>=0 triples per l)
__device__ const int c_T[21] = {0,1,7,22,50,95,161,252,372,525,715,946,1222,1547,
                                1925,2360,2856,3417,4047,4750,5530};

// ---------------- Wigner-d via the reference s-sum, term-ratio recurrence ----------------
__device__ double wig_tab(int l, int m, int n, const double* cp, const double* sp) {
    int s0 = max(0, n - m), s1 = min(l + n, l - m);
    if (s1 < s0) return 0.0;
    double pref = 0.5 * (g_lg[l+m] + g_lg[l-m] + g_lg[l+n] + g_lg[l-n]);
    double C = exp(pref - (g_lg[l+n-s0] + g_lg[s0] + g_lg[m-n+s0] + g_lg[l-m-s0]));
    double sg = ((m - n + s0) & 1) ? -1.0 : 1.0;
    int A = 2*l + n - m - 2*s0;   // cos^A
    int B = m - n + 2*s0;         // sin^B   (A+B = 2l <= 38)
    double val = 0.0;
    for (int s = s0; s <= s1; s++) {
        val += sg * C * cp[A] * sp[B];
        C  *= (double)((l + n - s) * (l - m - s)) / (double)((s + 1) * (m - n + s + 1));
        sg = -sg; A -= 2; B += 2;
    }
    return val;
}

__device__ double dpow_int(double x, int e) { double r = 1.0; for (int i = 0; i < e; i++) r *= x; return r; }

__device__ double wig_pow(int l, int m, int n, double cb, double sb) {
    int s0 = max(0, n - m), s1 = min(l + n, l - m);
    if (s1 < s0) return 0.0;
    double pref = 0.5 * (g_lg[l+m] + g_lg[l-m] + g_lg[l+n] + g_lg[l-n]);
    double C = exp(pref - (g_lg[l+n-s0] + g_lg[s0] + g_lg[m-n+s0] + g_lg[l-m-s0]));
    double sg = ((m - n + s0) & 1) ? -1.0 : 1.0;
    int A = 2*l + n - m - 2*s0, B = m - n + 2*s0;
    double cbA = dpow_int(cb, A), sbB = dpow_int(sb, B);
    double ci = 1.0 / (cb * cb), s2 = sb * sb;
    double val = 0.0;
    for (int s = s0; s <= s1; s++) {
        val += sg * C * cbA * sbB;
        C  *= (double)((l + n - s) * (l - m - s)) / (double)((s + 1) * (m - n + s + 1));
        sg = -sg; cbA *= ci; sbB *= s2;
    }
    return val;
}

// ---------------- constant-setup kernels ----------------
__global__ void k_init() {
    int t = threadIdx.x;  // 128 threads
    if (t == 0) {
        double a = 0.0; g_lg[0] = 0.0;
        for (int k = 1; k < 64; k++) { a += log((double)k); g_lg[k] = a; }
    }
    {   // input betas / quadrature
        double th = PI_D * (2*t + 1) / 256.0;
        double s = 0.0;
        for (int k = 0; k < 64; k++) s += sin((2*k + 1) * th) / (double)(2*k + 1);
        g_wq[t] = (2.0 / 64.0) * sin(th) * s;
        double cb = cos(0.5 * th), sb = sin(0.5 * th);
        double cp = 1.0, sp = 1.0;
        for (int k = 0; k < 40; k++) { g_cpin[t][k] = cp; g_spin[t][k] = sp; cp *= cb; sp *= sb; }
        double ang = 2.0 * PI_D * t / 128.0;
        g_tw128[t] = make_float2((float)cos(ang), (float)(-sin(ang)));
    }
    if (t < 40) {   // output betas
        double th = PI_D * (2*t + 1) / 80.0;
        double cb = cos(0.5 * th), sb = sin(0.5 * th);
        double cp = 1.0, sp = 1.0;
        for (int k = 0; k < 40; k++) { g_cpout[t][k] = cp; g_spout[t][k] = sp; cp *= cb; sp *= sb; }
        double ang = 2.0 * PI_D * t / 40.0;
        g_e40f[t] = make_float2((float)cos(ang), (float)sin(ang));
    }
}

__global__ void k_ws2() {
    int lmh = blockIdx.x, j = threadIdx.x;                    // 210 x 128
    int l = 0; while ((l + 1) * (l + 2) / 2 <= lmh) l++;
    int m = lmh - l * (l + 1) / 2;
    double d = wig_tab(l, m, 0, g_cpin[j], g_spin[j]);
    g_ws2[lmh * 128 + j] = (float)(d * g_wq[j]);
}

__global__ void k_dinv() {
    int t = blockIdx.x, b = threadIdx.x;                      // 5530 x 40
    int l = 0; while (c_T[l + 1] <= t) l++;
    int r = t - c_T[l];
    int m = r / (2*l + 1);
    int n = r % (2*l + 1) - l;
    double d = wig_tab(l, m, n, g_cpout[b], g_spout[b]) * (double)(2*l + 1);
    g_dinv[b * 5530 + t] = (float)d;
}

__global__ void k_fk() {
    int p = blockIdx.x, lmf = threadIdx.x;                    // 24 x 400
    int l = 0; while ((l + 1) * (l + 1) <= lmf) l++;
    int m = lmf - l * l - l;
    double beta  = (p / 8 + 1) * (PI_D / 24.0);
    double alpha = (p % 8) * (PI_D / 4.0);
    double cb = cos(0.5 * beta), sb = sin(0.5 * beta);
    double d = wig_pow(l, m, 0, cb, sb);
    double sn, cn; sincos(-(double)m * alpha, &sn, &cn);
    g_Fk[p * 400 + lmf] = make_float2((float)(d * cn), (float)(d * sn));
}

__global__ void k_y(const float* __restrict__ ker) {
    __shared__ float2 sFk[24];
    int lmf = blockIdx.x, io = threadIdx.x;                   // 400 x 512
    if (io < 24) sFk[io] = g_Fk[io * 400 + lmf];
    __syncthreads();
    const float sc = 0.008164965809277261f;                   // 1/sqrt(15000)
    float ar = 0.f, ai = 0.f;
    #pragma unroll
    for (int p = 0; p < 24; p++) {
        float k = ker[io * 24 + p];
        ar = fmaf(k, sFk[p].x, ar);
        ai = fmaf(k, sFk[p].y, ai);
    }
    g_y[lmf * 512 + io] = make_float2(sc * ar, sc * ai);
}

// ---------------- main pipeline ----------------
// xf[m][j][zi] = sum_a x[zi][j][a] e^{-2pi i m a/128},   m = 0..19
__global__ void kx1(const float* __restrict__ x) {
    __shared__ float2 tw[128];
    int tid = threadIdx.x;
    if (tid < 128) tw[tid] = g_tw128[tid];
    __syncthreads();
    int warp = tid >> 5, lane = tid & 31;
    int row = blockIdx.x * 8 + warp;        // zi*128 + j
    int zi = row >> 7, j = row & 127;
    const float* xr = x + (size_t)row * 128;
    float xv0 = xr[lane], xv1 = xr[lane + 32], xv2 = xr[lane + 64], xv3 = xr[lane + 96];
    for (int m = 0; m < 20; m++) {
        int i0 = (m * lane) & 127;
        int st = (m * 32) & 127;
        int i1 = (i0 + st) & 127, i2 = (i1 + st) & 127, i3 = (i2 + st) & 127;
        float2 t0 = tw[i0], t1 = tw[i1], t2 = tw[i2], t3 = tw[i3];
        float re = xv0 * t0.x + xv1 * t1.x + xv2 * t2.x + xv3 * t3.x;
        float im = xv0 * t0.y + xv1 * t1.y + xv2 * t2.y + xv3 * t3.y;
        #pragma unroll
        for (int o = 16; o; o >>= 1) {
            re += __shfl_xor_sync(0xffffffffu, re, o);
            im += __shfl_xor_sync(0xffffffffu, im, o);
        }
        if (lane == 0) g_xf[(m * 128 + j) * 256 + zi] = make_float2(re, im);
    }
}

// xl[lmh][zi] = sum_j ws2[lmh][j] * xf[m][j][zi]
__global__ void kx2() {
    __shared__ float sw[128];
    int lmh = blockIdx.x, zi = threadIdx.x;                   // 210 x 256
    if (zi < 128) sw[zi] = g_ws2[lmh * 128 + zi];
    __syncthreads();
    int l = 0; while ((l + 1) * (l + 2) / 2 <= lmh) l++;
    int m = lmh - l * (l + 1) / 2;
    const float2* base = g_xf + m * 128 * 256;
    float ar = 0.f, ai = 0.f;
    for (int j = 0; j < 128; j++) {
        float w = sw[j];
        float2 v = base[j * 256 + zi];
        ar = fmaf(w, v.x, ar);
        ai = fmaf(w, v.y, ai);
    }
    g_xl[lmh * 256 + zi] = make_float2(ar, ai);
}

// zl[t][z*32+o] = sum_i xl[lmh][z*16+i] * conj(y[lmf][i*32+o])
__global__ void kx3() {
    __shared__ float2 sx[256];
    __shared__ float2 sy[512];
    int t = blockIdx.x, tid = threadIdx.x;                    // 5530 x 512
    int l = 0; while (c_T[l + 1] <= t) l++;
    int r = t - c_T[l];
    int m = r / (2*l + 1), ni = r % (2*l + 1);
    int lmh = l * (l + 1) / 2 + m;
    int lmf = l * l + ni;
    if (tid < 256) sx[tid] = g_xl[lmh * 256 + tid];
    sy[tid] = g_y[lmf * 512 + tid];
    __syncthreads();
    int z = tid >> 5, o = tid & 31;
    float ar = 0.f, ai = 0.f;
    #pragma unroll
    for (int i = 0; i < 16; i++) {
        float2 xv = sx[z * 16 + i];
        float2 yv = sy[i * 32 + o];
        ar += xv.x * yv.x + xv.y * yv.y;      // x * conj(y)
        ai += xv.y * yv.x - xv.x * yv.y;
    }
    g_zl[t * 512 + tid] = make_float2(ar, ai);
}

// fused: O_m[n] contraction over l  ->  n-DFT  ->  Hermitian m-accumulation into f registers
__global__ void __launch_bounds__(320) kx4(float* __restrict__ out, const float* __restrict__ bias) {
    __shared__ float2 sOm[39 * 8];
    __shared__ float2 sGm[40 * 8];
    __shared__ float2 se[40];
    int tid = threadIdx.x;
    int b = blockIdx.y;
    int zo0 = blockIdx.x * 8;
    if (tid < 40) se[tid] = g_e40f[tid];
    int nidx = tid >> 3, zol = tid & 7;     // nidx: n-slot / g / a depending on stage
    float f[40];
    #pragma unroll
    for (int g = 0; g < 40; g++) f[g] = 0.f;
    __syncthreads();

    for (int m = 0; m < 20; m++) {
        // ---- stage 1: Om[n][zo] = sum_{l>=max(m,|n|)} dinv[b][l,m,n] * zl[l,m,n][zo]
        if (nidx < 39) {
            int n = nidx - 19;
            int an = n < 0 ? -n : n;
            int lmin = m > an ? m : an;
            float orr = 0.f, oii = 0.f;
            for (int l = lmin; l < 20; l++) {
                int tt = c_T[l] + m * (2*l + 1) + (n + l);
                float d = g_dinv[b * 5530 + tt];
                float2 zv = g_zl[tt * 512 + zo0 + zol];
                orr = fmaf(d, zv.x, orr);
                oii = fmaf(d, zv.y, oii);
            }
            sOm[nidx * 8 + zol] = make_float2(orr, oii);
        }
        __syncthreads();
        // ---- stage 2: Gm[g][zo] = sum_n Om[n][zo] e^{+2pi i n g/40}
        {
            int g = nidx;                   // 0..39
            float gr = 0.f, gi = 0.f;
            int idx = (21 * g) % 40;        // n=-19 == +21 (mod 40)
            for (int nn = 0; nn < 39; nn++) {
                float2 e = se[idx];
                float2 om = sOm[nn * 8 + zol];
                gr += om.x * e.x - om.y * e.y;
                gi += om.x * e.y + om.y * e.x;
                idx += g; if (idx >= 40) idx -= 40;
            }
            sGm[g * 8 + zol] = make_float2(gr, gi);
        }
        __syncthreads();
        // ---- stage 3: f[a][g] += w_m * Re( e^{+2pi i m a/40} * Gm[g] )
        {
            int a = nidx;
            float2 e = se[(m * a) % 40];
            float w = (m == 0) ? 1.f : 2.f;
            float wc = w * e.x, ws = w * e.y;
            #pragma unroll
            for (int g = 0; g < 40; g++) {
                float2 gm = sGm[g * 8 + zol];
                f[g] += wc * gm.x - ws * gm.y;
            }
        }
        __syncthreads();
    }

    // ---- write out: out[zo][b][a][g] + bias[o]
    int zo = zo0 + zol;
    int a = nidx;
    float bv = bias[zo & 31];
    float* op = out + ((size_t)zo * 40 + b) * 1600 + a * 40;
    float4* op4 = (float4*)op;
    #pragma unroll
    for (int g4 = 0; g4 < 10; g4++) {
        op4[g4] = make_float4(f[4*g4] + bv, f[4*g4 + 1] + bv, f[4*g4 + 2] + bv, f[4*g4 + 3] + bv);
    }
}

// ---------------- launch ----------------
extern "C" void kernel_launch(void* const* d_in, const int* in_sizes, int n_in,
                              void* d_out, int out_size) {
    const float* x    = (const float*)d_in[0];
    const float* ker  = (const float*)d_in[1];
    const float* bias = (const float*)d_in[2];
    float* out = (float*)d_out;

    k_init<<<1, 128>>>();
    k_ws2 <<<210, 128>>>();
    k_dinv<<<5530, 40>>>();
    k_fk  <<<24, 400>>>();
    k_y   <<<400, 512>>>(ker);

    kx1<<<4096, 256>>>(x);
    kx2<<<210, 256>>>();
    kx3<<<5530, 512>>>();
    kx4<<<dim3(64, 40), 320>>>(out, bias);
}

// round 3
// speedup vs baseline: 1.1034x; 1.1034x over previous
#include <cuda_runtime.h>
#include <math.h>

#define PI_D 3.141592653589793238462643383279502884

// ---------------- constant / scratch device globals ----------------
__device__ double g_lg[64];            // log(k!)
__device__ double g_wq[128];           // SOFT quadrature weights
__device__ float2 g_tw128[128];        // e^{-2pi i t/128}
__device__ float2 g_e40f[40];          // e^{+2pi i t/40}

__device__ float  g_ws2 [210*128];     // [lmh][j], m>=0 half, quadrature-weighted d^l_{m,0}
__device__ float  g_dinv[40*5530];     // [b][t], (2l+1)*d^l_{m,n}(beta_b), m>=0 half
__device__ float2 g_y   [400*512];     // [lmf][i*32+o]
__device__ float2 g_xf  [20*128*256];  // [m][j][zi]
__device__ float2 g_xl  [210*256];     // [lmh][zi]
__device__ float2 g_zl  [5530*512];    // [t][z*32+o]

// prefix offsets T_l = sum_{k<l} (k+1)(2k+1)  (m>=0 triples per l)
__device__ const int c_T[21] = {0,1,7,22,50,95,161,252,372,525,715,946,1222,1547,
                                1925,2360,2856,3417,4047,4750,5530};

__device__ double dpow_int(double x, int e) { double r = 1.0; for (int i = 0; i < e; i++) r *= x; return r; }

// full Wigner s-sum, per-thread (used only for the small F_k set: 9600 evals)
__device__ double wig_pow(int l, int m, int n, double cb, double sb) {
    int s0 = max(0, n - m), s1 = min(l + n, l - m);
    if (s1 < s0) return 0.0;
    double pref = 0.5 * (g_lg[l+m] + g_lg[l-m] + g_lg[l+n] + g_lg[l-n]);
    double C = exp(pref - (g_lg[l+n-s0] + g_lg[s0] + g_lg[m-n+s0] + g_lg[l-m-s0]));
    double sg = ((m - n + s0) & 1) ? -1.0 : 1.0;
    int A = 2*l + n - m - 2*s0, B = m - n + 2*s0;
    double cbA = dpow_int(cb, A), sbB = dpow_int(sb, B);
    double ci = 1.0 / (cb * cb), s2 = sb * sb;
    double val = 0.0;
    for (int s = s0; s <= s1; s++) {
        val += sg * C * cbA * sbB;
        C  *= (double)((l + n - s) * (l - m - s)) / (double)((s + 1) * (m - n + s + 1));
        sg = -sg; cbA *= ci; sbB *= s2;
    }
    return val;
}

// ---------------- setup kernels ----------------
__global__ void k_init() {
    int t = threadIdx.x;  // 128
    if (t == 0) {
        double a = 0.0; g_lg[0] = 0.0;
        for (int k = 1; k < 64; k++) { a += log((double)k); g_lg[k] = a; }
    }
    {
        double th = PI_D * (2*t + 1) / 256.0;
        double s = 0.0;
        for (int k = 0; k < 64; k++) s += sin((2*k + 1) * th) / (double)(2*k + 1);
        g_wq[t] = (2.0 / 64.0) * sin(th) * s;
        double ang = 2.0 * PI_D * t / 128.0;
        g_tw128[t] = make_float2((float)cos(ang), (float)(-sin(ang)));
    }
    if (t < 40) {
        double ang = 2.0 * PI_D * t / 40.0;
        g_e40f[t] = make_float2((float)cos(ang), (float)sin(ang));
    }
}

// fused ws2 + dinv: per-block coefficient precompute (1 exp + <=20 div per BLOCK),
// then pure mul/fma per beta sample.
__global__ void k_sd() {
    __shared__ double scoef[24];
    int blk = blockIdx.x;
    if (blk < 210) {
        // ---- ws2 task: lmh = blk, n = 0 ----
        int lmh = blk;
        int l = 0; while ((l + 1) * (l + 2) / 2 <= lmh) l++;
        int m = lmh - l * (l + 1) / 2;
        int s1 = l - m;                       // s0 = 0
        if (threadIdx.x == 0) {
            double pref = 0.5 * (g_lg[l+m] + g_lg[l-m]) + g_lg[l];
            double C = exp(pref - (g_lg[l] + g_lg[m] + g_lg[l-m]));
            double sg = (m & 1) ? -1.0 : 1.0;
            for (int s = 0; s <= s1; s++) {
                scoef[s] = sg * C;
                C *= (double)((l - s) * (l - m - s)) / (double)((s + 1) * (m + s + 1));
                sg = -sg;
            }
        }
        __syncthreads();
        int j = threadIdx.x;                  // 0..127
        double th = PI_D * (2*j + 1) / 256.0;
        double cb = cos(0.5 * th), sb = sin(0.5 * th);
        double cbA = dpow_int(cb, 2*l - m), sbB = dpow_int(sb, m);
        double ci = 1.0 / (cb * cb), s2 = sb * sb;
        double val = 0.0;
        for (int s = 0; s <= s1; s++) { val += scoef[s] * cbA * sbB; cbA *= ci; sbB *= s2; }
        g_ws2[lmh * 128 + j] = (float)(val * g_wq[j]);
    } else {
        // ---- dinv task: t = blk - 210 ----
        int t = blk - 210;
        int l = 0; while (c_T[l + 1] <= t) l++;
        int r = t - c_T[l];
        int m = r / (2*l + 1);
        int n = r % (2*l + 1) - l;
        int s0 = max(0, n - m), s1 = min(l + n, l - m);
        if (threadIdx.x == 0) {
            double pref = 0.5 * (g_lg[l+m] + g_lg[l-m] + g_lg[l+n] + g_lg[l-n]);
            double C = exp(pref - (g_lg[l+n-s0] + g_lg[s0] + g_lg[m-n+s0] + g_lg[l-m-s0]));
            double sg = ((m - n + s0) & 1) ? -1.0 : 1.0;
            for (int s = s0; s <= s1; s++) {
                scoef[s - s0] = sg * C;
                C *= (double)((l + n - s) * (l - m - s)) / (double)((s + 1) * (m - n + s + 1));
                sg = -sg;
            }
        }
        __syncthreads();
        int b = threadIdx.x;
        if (b < 40) {
            double th = PI_D * (2*b + 1) / 80.0;
            double cb = cos(0.5 * th), sb = sin(0.5 * th);
            int A0 = 2*l + n - m - 2*s0, B0 = m - n + 2*s0;
            double cbA = dpow_int(cb, A0), sbB = dpow_int(sb, B0);
            double ci = 1.0 / (cb * cb), s2 = sb * sb;
            double val = 0.0;
            int nt = s1 - s0;
            for (int s = 0; s <= nt; s++) { val += scoef[s] * cbA * sbB; cbA *= ci; sbB *= s2; }
            g_dinv[b * 5530 + t] = (float)(val * (double)(2*l + 1));
        }
    }
}

// y[lmf][io] : F_k column computed in-block (24 wigner evals), then kernel dot
__global__ void k_y(const float* __restrict__ ker) {
    __shared__ float2 sFk[24];
    int lmf = blockIdx.x, io = threadIdx.x;                   // 400 x 512
    int l = 0; while ((l + 1) * (l + 1) <= lmf) l++;
    int m = lmf - l * l - l;
    if (io < 24) {
        double beta  = (io / 8 + 1) * (PI_D / 24.0);
        double alpha = (io % 8) * (PI_D / 4.0);
        double cb = cos(0.5 * beta), sb = sin(0.5 * beta);
        double d = wig_pow(l, m, 0, cb, sb);
        double sn, cn; sincos(-(double)m * alpha, &sn, &cn);
        sFk[io] = make_float2((float)(d * cn), (float)(d * sn));
    }
    __syncthreads();
    const float sc = 0.008164965809277261f;                   // 1/sqrt(15000)
    float ar = 0.f, ai = 0.f;
    #pragma unroll
    for (int p = 0; p < 24; p++) {
        float k = ker[io * 24 + p];
        ar = fmaf(k, sFk[p].x, ar);
        ai = fmaf(k, sFk[p].y, ai);
    }
    g_y[lmf * 512 + io] = make_float2(sc * ar, sc * ai);
}

// ---------------- main pipeline ----------------
__global__ void kx1(const float* __restrict__ x) {
    __shared__ float2 tw[128];
    int tid = threadIdx.x;
    if (tid < 128) tw[tid] = g_tw128[tid];
    __syncthreads();
    int warp = tid >> 5, lane = tid & 31;
    int row = blockIdx.x * 8 + warp;        // zi*128 + j
    int zi = row >> 7, j = row & 127;
    const float* xr = x + (size_t)row * 128;
    float xv0 = xr[lane], xv1 = xr[lane + 32], xv2 = xr[lane + 64], xv3 = xr[lane + 96];
    for (int m = 0; m < 20; m++) {
        int i0 = (m * lane) & 127;
        int st = (m * 32) & 127;
        int i1 = (i0 + st) & 127, i2 = (i1 + st) & 127, i3 = (i2 + st) & 127;
        float2 t0 = tw[i0], t1 = tw[i1], t2 = tw[i2], t3 = tw[i3];
        float re = xv0 * t0.x + xv1 * t1.x + xv2 * t2.x + xv3 * t3.x;
        float im = xv0 * t0.y + xv1 * t1.y + xv2 * t2.y + xv3 * t3.y;
        #pragma unroll
        for (int o = 16; o; o >>= 1) {
            re += __shfl_xor_sync(0xffffffffu, re, o);
            im += __shfl_xor_sync(0xffffffffu, im, o);
        }
        if (lane == 0) g_xf[(m * 128 + j) * 256 + zi] = make_float2(re, im);
    }
}

__global__ void kx2() {
    __shared__ float sw[128];
    int lmh = blockIdx.x, zi = threadIdx.x;                   // 210 x 256
    if (zi < 128) sw[zi] = g_ws2[lmh * 128 + zi];
    __syncthreads();
    int l = 0; while ((l + 1) * (l + 2) / 2 <= lmh) l++;
    int m = lmh - l * (l + 1) / 2;
    const float2* base = g_xf + m * 128 * 256;
    float ar = 0.f, ai = 0.f;
    for (int j = 0; j < 128; j++) {
        float w = sw[j];
        float2 v = base[j * 256 + zi];
        ar = fmaf(w, v.x, ar);
        ai = fmaf(w, v.y, ai);
    }
    g_xl[lmh * 256 + zi] = make_float2(ar, ai);
}

__global__ void kx3() {
    __shared__ float2 sx[256];
    __shared__ float2 sy[512];
    int t = blockIdx.x, tid = threadIdx.x;                    // 5530 x 512
    int l = 0; while (c_T[l + 1] <= t) l++;
    int r = t - c_T[l];
    int m = r / (2*l + 1), ni = r % (2*l + 1);
    int lmh = l * (l + 1) / 2 + m;
    int lmf = l * l + ni;
    if (tid < 256) sx[tid] = g_xl[lmh * 256 + tid];
    sy[tid] = g_y[lmf * 512 + tid];
    __syncthreads();
    int z = tid >> 5, o = tid & 31;
    float ar = 0.f, ai = 0.f;
    #pragma unroll
    for (int i = 0; i < 16; i++) {
        float2 xv = sx[z * 16 + i];
        float2 yv = sy[i * 32 + o];
        ar += xv.x * yv.x + xv.y * yv.y;      // x * conj(y)
        ai += xv.y * yv.x - xv.x * yv.y;
    }
    g_zl[t * 512 + tid] = make_float2(ar, ai);
}

// fused synthesis, b tiled by 2
__global__ void __launch_bounds__(320) kx4(float* __restrict__ out, const float* __restrict__ bias) {
    __shared__ float2 sOm[2][39 * 8];
    __shared__ float2 sGm[2][40 * 8];
    __shared__ float2 se[40];
    int tid = threadIdx.x;
    int b0 = blockIdx.y * 2;
    int zo0 = blockIdx.x * 8;
    if (tid < 40) se[tid] = g_e40f[tid];
    int nidx = tid >> 3, zol = tid & 7;
    float f0[40], f1[40];
    #pragma unroll
    for (int g = 0; g < 40; g++) { f0[g] = 0.f; f1[g] = 0.f; }
    __syncthreads();

    for (int m = 0; m < 20; m++) {
        // ---- stage 1: Om[n][zo] = sum_l dinv[b][l,m,n] * zl[l,m,n][zo], for b0 and b0+1
        if (nidx < 39) {
            int n = nidx - 19;
            int an = n < 0 ? -n : n;
            int lmin = m > an ? m : an;
            float o0r = 0.f, o0i = 0.f, o1r = 0.f, o1i = 0.f;
            for (int l = lmin; l < 20; l++) {
                int tt = c_T[l] + m * (2*l + 1) + (n + l);
                float d0 = g_dinv[b0 * 5530 + tt];
                float d1 = g_dinv[(b0 + 1) * 5530 + tt];
                float2 zv = g_zl[tt * 512 + zo0 + zol];
                o0r = fmaf(d0, zv.x, o0r);
                o0i = fmaf(d0, zv.y, o0i);
                o1r = fmaf(d1, zv.x, o1r);
                o1i = fmaf(d1, zv.y, o1i);
            }
            sOm[0][nidx * 8 + zol] = make_float2(o0r, o0i);
            sOm[1][nidx * 8 + zol] = make_float2(o1r, o1i);
        }
        __syncthreads();
        // ---- stage 2: Gm[g][zo] = sum_n Om[n][zo] e^{+2pi i n g/40}
        {
            int g = nidx;
            float g0r = 0.f, g0i = 0.f, g1r = 0.f, g1i = 0.f;
            int idx = (21 * g) % 40;        // n=-19 == +21 (mod 40)
            for (int nn = 0; nn < 39; nn++) {
                float2 e = se[idx];
                float2 a0 = sOm[0][nn * 8 + zol];
                float2 a1 = sOm[1][nn * 8 + zol];
                g0r += a0.x * e.x - a0.y * e.y;
                g0i += a0.x * e.y + a0.y * e.x;
                g1r += a1.x * e.x - a1.y * e.y;
                g1i += a1.x * e.y + a1.y * e.x;
                idx += g; if (idx >= 40) idx -= 40;
            }
            sGm[0][g * 8 + zol] = make_float2(g0r, g0i);
            sGm[1][g * 8 + zol] = make_float2(g1r, g1i);
        }
        __syncthreads();
        // ---- stage 3: f[a][g] += w_m * Re( e^{+2pi i m a/40} * Gm[g] )
        {
            int a = nidx;
            float2 e = se[(m * a) % 40];
            float w = (m == 0) ? 1.f : 2.f;
            float wc = w * e.x, ws = w * e.y;
            #pragma unroll
            for (int g = 0; g < 40; g++) {
                float2 gm0 = sGm[0][g * 8 + zol];
                float2 gm1 = sGm[1][g * 8 + zol];
                f0[g] += wc * gm0.x - ws * gm0.y;
                f1[g] += wc * gm1.x - ws * gm1.y;
            }
        }
        __syncthreads();
    }

    // ---- write out: out[zo][b][a][g] + bias[o]
    int zo = zo0 + zol;
    int a = nidx;
    float bv = bias[zo & 31];
    float* op0 = out + ((size_t)zo * 40 + b0) * 1600 + a * 40;
    float* op1 = op0 + 1600;
    float4* o40 = (float4*)op0;
    float4* o41 = (float4*)op1;
    #pragma unroll
    for (int g4 = 0; g4 < 10; g4++) {
        o40[g4] = make_float4(f0[4*g4] + bv, f0[4*g4 + 1] + bv, f0[4*g4 + 2] + bv, f0[4*g4 + 3] + bv);
        o41[g4] = make_float4(f1[4*g4] + bv, f1[4*g4 + 1] + bv, f1[4*g4 + 2] + bv, f1[4*g4 + 3] + bv);
    }
}

// ---------------- launch ----------------
extern "C" void kernel_launch(void* const* d_in, const int* in_sizes, int n_in,
                              void* d_out, int out_size) {
    const float* x    = (const float*)d_in[0];
    const float* ker  = (const float*)d_in[1];
    const float* bias = (const float*)d_in[2];
    float* out = (float*)d_out;

    k_init<<<1, 128>>>();
    k_sd  <<<5740, 128>>>();
    k_y   <<<400, 512>>>(ker);

    kx1<<<4096, 256>>>(x);
    kx2<<<210, 256>>>();
    kx3<<<5530, 512>>>();
    kx4<<<dim3(64, 20), 320>>>(out, bias);
}